// round 1
// baseline (speedup 1.0000x reference)
#include <cuda_runtime.h>
#include <math.h>
#include <stdint.h>

// ---------------- problem dims ----------------
#define B_   8
#define S_   4096
#define D_   512
#define H_   1024
#define Kc_  4
#define CS_  64
#define NC_  64
#define BS_  (B_ * S_)      // 32768 tokens
#define R_   (B_ * CS_)     // 512 rows per chunk
#define ERR_CLIP  1.0f
#define GRAD_CLIP 1.0f
#define SCALE_    (2.0f / (float)CS_)   // 0.03125

// ---------------- device scratch (static: no runtime alloc) ----------------
__device__ float g_proj [(size_t)BS_ * D_];   // pre-conv projection scratch
__device__ float g_kc   [(size_t)BS_ * D_];   // k, chunk-major [NC][B][CS][D]
__device__ float g_vc   [(size_t)BS_ * D_];
__device__ float g_qc   [(size_t)BS_ * D_];
__device__ float g_ych  [(size_t)BS_ * D_];   // retrieval output, chunk-major
__device__ float g_yfl  [(size_t)BS_ * D_];   // flat [B,S,D]
__device__ float g_h1   [(size_t)R_ * H_];
__device__ float g_a1   [(size_t)R_ * H_];
__device__ float g_sd   [(size_t)R_ * H_];
__device__ float g_d1   [(size_t)R_ * H_];
__device__ float g_tb   [(size_t)R_ * H_];
__device__ float g_d2   [(size_t)R_ * D_];
__device__ float g_g1   [(size_t)H_ * D_];
__device__ float g_g2   [(size_t)D_ * H_];
__device__ float g_Wd1  [(size_t)H_ * D_];
__device__ float g_M1   [(size_t)H_ * D_];
__device__ float g_Wd2  [(size_t)D_ * H_];
__device__ float g_M2   [(size_t)D_ * H_];
__device__ float g_alpha[NC_];
__device__ float g_lrg  [NC_];
__device__ float g_eta  [NC_];

// ---------------- generic tiled fp32 GEMM ----------------
// MODE 0 (NT): C[M,N] = A[M,K] * B[N,K]^T
// MODE 1 (NN): C[M,N] = A[M,K] * B[K,N]
// MODE 2 (TN): C[M,N] = A[K,M]^T * B[K,N]
// If BSUM: effective B element = B0[i] + B1[i] (same layout)
#define TILE 64
#define BK   16

template <int MODE, bool BSUM>
__global__ void __launch_bounds__(256)
gemm_kernel(const float* __restrict__ A, const float* __restrict__ B0,
            const float* __restrict__ B1, float* __restrict__ C,
            int M, int N, int K)
{
    __shared__ float As[BK][TILE + 4];
    __shared__ float Bs[BK][TILE + 4];
    const int tid = threadIdx.x;
    const int tx = tid & 15;
    const int ty = tid >> 4;
    const int m0 = blockIdx.y * TILE;
    const int n0 = blockIdx.x * TILE;

    float acc[4][4] = {};

    for (int k0 = 0; k0 < K; k0 += BK) {
        // --- load A tile into As[k][m] ---
        if (MODE == 2) {
            // A[K,M]: direct
            const int kk = tid >> 4;
            const int mv = (tid & 15) << 2;
            const float4 a = *(const float4*)(A + (size_t)(k0 + kk) * M + m0 + mv);
            As[kk][mv + 0] = a.x; As[kk][mv + 1] = a.y;
            As[kk][mv + 2] = a.z; As[kk][mv + 3] = a.w;
        } else {
            // A[M,K]: transpose on store
            const int mm = tid >> 2;
            const int kv = (tid & 3) << 2;
            const float4 a = *(const float4*)(A + (size_t)(m0 + mm) * K + k0 + kv);
            As[kv + 0][mm] = a.x; As[kv + 1][mm] = a.y;
            As[kv + 2][mm] = a.z; As[kv + 3][mm] = a.w;
        }
        // --- load B tile into Bs[k][n] ---
        if (MODE == 0) {
            // B[N,K]: transpose on store
            const int nn = tid >> 2;
            const int kv = (tid & 3) << 2;
            const size_t off = (size_t)(n0 + nn) * K + k0 + kv;
            float4 b = *(const float4*)(B0 + off);
            if (BSUM) {
                const float4 c4 = *(const float4*)(B1 + off);
                b.x += c4.x; b.y += c4.y; b.z += c4.z; b.w += c4.w;
            }
            Bs[kv + 0][nn] = b.x; Bs[kv + 1][nn] = b.y;
            Bs[kv + 2][nn] = b.z; Bs[kv + 3][nn] = b.w;
        } else {
            // B[K,N]: direct
            const int kk = tid >> 4;
            const int nv = (tid & 15) << 2;
            const size_t off = (size_t)(k0 + kk) * N + n0 + nv;
            float4 b = *(const float4*)(B0 + off);
            if (BSUM) {
                const float4 c4 = *(const float4*)(B1 + off);
                b.x += c4.x; b.y += c4.y; b.z += c4.z; b.w += c4.w;
            }
            Bs[kk][nv + 0] = b.x; Bs[kk][nv + 1] = b.y;
            Bs[kk][nv + 2] = b.z; Bs[kk][nv + 3] = b.w;
        }
        __syncthreads();

#pragma unroll
        for (int kk = 0; kk < BK; kk++) {
            float av[4], bv[4];
#pragma unroll
            for (int i = 0; i < 4; i++) av[i] = As[kk][ty + 16 * i];
#pragma unroll
            for (int j = 0; j < 4; j++) bv[j] = Bs[kk][tx + 16 * j];
#pragma unroll
            for (int i = 0; i < 4; i++)
#pragma unroll
                for (int j = 0; j < 4; j++)
                    acc[i][j] = fmaf(av[i], bv[j], acc[i][j]);
        }
        __syncthreads();
    }

#pragma unroll
    for (int i = 0; i < 4; i++) {
        const size_t m = (size_t)m0 + ty + 16 * i;
#pragma unroll
        for (int j = 0; j < 4; j++)
            C[m * N + n0 + tx + 16 * j] = acc[i][j];
    }
}

static void launch_gemm(int mode, bool bsum,
                        const float* A, const float* B0, const float* B1,
                        float* C, int M, int N, int K)
{
    dim3 grid(N / TILE, M / TILE), block(256);
    if (mode == 0) {
        if (bsum) gemm_kernel<0, true ><<<grid, block>>>(A, B0, B1, C, M, N, K);
        else      gemm_kernel<0, false><<<grid, block>>>(A, B0, B1, C, M, N, K);
    } else if (mode == 1) {
        if (bsum) gemm_kernel<1, true ><<<grid, block>>>(A, B0, B1, C, M, N, K);
        else      gemm_kernel<1, false><<<grid, block>>>(A, B0, B1, C, M, N, K);
    } else {
        if (bsum) gemm_kernel<2, true ><<<grid, block>>>(A, B0, B1, C, M, N, K);
        else      gemm_kernel<2, false><<<grid, block>>>(A, B0, B1, C, M, N, K);
    }
}

// ---------------- elementwise kernels ----------------
__device__ __forceinline__ float sigm(float x) { return 1.0f / (1.0f + __expf(-x)); }

__global__ void zero_state_kernel()
{
    const size_t i = (size_t)blockIdx.x * blockDim.x + threadIdx.x;
    if (i < (size_t)H_ * D_) {
        g_Wd1[i] = 0.f; g_M1[i] = 0.f; g_Wd2[i] = 0.f; g_M2[i] = 0.f;
    }
}

// a = silu(h); sd = silu'(h)
__global__ void silu_fwd_kernel(const float* __restrict__ h, float* __restrict__ a,
                                float* __restrict__ sd, int n)
{
    const int i = blockIdx.x * blockDim.x + threadIdx.x;
    if (i >= n) return;
    const float x = h[i];
    const float s = sigm(x);
    a[i]  = x * s;
    sd[i] = s * (1.0f + x * (1.0f - s));
}

// d2 = SCALE * clip(pred - v)
__global__ void make_d2_kernel(float* __restrict__ p, const float* __restrict__ v, int n)
{
    const int i = blockIdx.x * blockDim.x + threadIdx.x;
    if (i >= n) return;
    const float e = fminf(fmaxf(p[i] - v[i], -ERR_CLIP), ERR_CLIP);
    p[i] = SCALE_ * e;
}

__global__ void mul_inplace_kernel(float* __restrict__ a, const float* __restrict__ b, int n)
{
    const int i = blockIdx.x * blockDim.x + threadIdx.x;
    if (i >= n) return;
    a[i] *= b[i];
}

// gc = clip(g); M = eta*M - lr*gc; Wd = (1-a)*Wd + M
__global__ void apply_update_kernel(const float* __restrict__ g, float* __restrict__ Mo,
                                    float* __restrict__ Wd, int c, int n)
{
    const int i = blockIdx.x * blockDim.x + threadIdx.x;
    if (i >= n) return;
    const float a = g_alpha[c], l = g_lrg[c], e = g_eta[c];
    const float gc = fminf(fmaxf(g[i], -GRAD_CLIP), GRAD_CLIP);
    const float m = e * Mo[i] - l * gc;
    Mo[i] = m;
    Wd[i] = (1.0f - a) * Wd[i] + m;
}

__global__ void silu_inplace_kernel(float* __restrict__ t, int n)
{
    const int i = blockIdx.x * blockDim.x + threadIdx.x;
    if (i >= n) return;
    const float x = t[i];
    t[i] = x * sigm(x);
}

// causal depthwise conv (left pad K-1), writes chunk-major [NC][B][CS][D]
__global__ void conv_chunk_kernel(const float* __restrict__ in, const float* __restrict__ w,
                                  const float* __restrict__ bias, float* __restrict__ out)
{
    const size_t i = (size_t)blockIdx.x * blockDim.x + threadIdx.x;
    if (i >= (size_t)BS_ * D_) return;
    const int d = (int)(i & (D_ - 1));
    const size_t bs = i >> 9;            // b*S + s
    const int s = (int)(bs & (S_ - 1));
    const int b = (int)(bs >> 12);
    float acc = bias[d];
#pragma unroll
    for (int j = 0; j < Kc_; j++) {
        const int sp = s - (Kc_ - 1) + j;
        if (sp >= 0)
            acc = fmaf(w[d * Kc_ + j], in[((size_t)b * S_ + sp) * D_ + d], acc);
    }
    const int c  = s >> 6;
    const int cs = s & 63;
    out[((((size_t)c * B_ + b) * CS_ + cs) << 9) + d] = acc;
}

// per-chunk scalar gates: sigmoid(x.w + b) mean-pooled over (B, CS)
__global__ void gates_kernel(const float* __restrict__ x,
                             const float* __restrict__ wd, const float* __restrict__ bd,
                             const float* __restrict__ wl, const float* __restrict__ bl,
                             const float* __restrict__ we, const float* __restrict__ be)
{
    const int c = blockIdx.x;
    const int t = threadIdx.x;          // 0..511
    const int b  = t >> 6;
    const int cs = t & 63;
    const float4* xr = (const float4*)(x + (((size_t)b * S_ + (size_t)c * CS_ + cs) << 9));
    const float4* w0 = (const float4*)wd;
    const float4* w1 = (const float4*)wl;
    const float4* w2 = (const float4*)we;
    float s0 = 0.f, s1 = 0.f, s2 = 0.f;
#pragma unroll 4
    for (int d = 0; d < D_ / 4; d++) {
        const float4 xv = xr[d];
        const float4 a0 = w0[d], a1 = w1[d], a2 = w2[d];
        s0 += xv.x * a0.x + xv.y * a0.y + xv.z * a0.z + xv.w * a0.w;
        s1 += xv.x * a1.x + xv.y * a1.y + xv.z * a1.z + xv.w * a1.w;
        s2 += xv.x * a2.x + xv.y * a2.y + xv.z * a2.z + xv.w * a2.w;
    }
    s0 = sigm(s0 + bd[0]);
    s1 = sigm(s1 + bl[0]);
    s2 = sigm(s2 + be[0]);

    __shared__ float r0[512], r1[512], r2[512];
    r0[t] = s0; r1[t] = s1; r2[t] = s2;
    __syncthreads();
    for (int off = 256; off > 0; off >>= 1) {
        if (t < off) { r0[t] += r0[t + off]; r1[t] += r1[t + off]; r2[t] += r2[t + off]; }
        __syncthreads();
    }
    if (t == 0) {
        g_alpha[c] = r0[0] * (1.0f / 512.0f);
        g_lrg[c]   = r1[0] * (1.0f / 512.0f);
        g_eta[c]   = r2[0] * (1.0f / 512.0f);
    }
}

// chunk-major -> flat [B,S,D]
__global__ void permute_y_kernel()
{
    const size_t i = (size_t)blockIdx.x * blockDim.x + threadIdx.x;
    if (i >= (size_t)BS_ * D_) return;
    const int d = (int)(i & (D_ - 1));
    const size_t r = i >> 9;
    const int s = (int)(r & (S_ - 1));
    const int b = (int)(r >> 12);
    const int c  = s >> 6;
    const int cs = s & 63;
    g_yfl[i] = g_ych[((((size_t)c * B_ + b) * CS_ + cs) << 9) + d];
}

// ---------------- entry point ----------------
extern "C" void kernel_launch(void* const* d_in, const int* in_sizes, int n_in,
                              void* d_out, int out_size)
{
    (void)in_sizes; (void)n_in; (void)out_size;
    const float* x    = (const float*)d_in[0];
    const float* Wk   = (const float*)d_in[1];
    const float* Wv   = (const float*)d_in[2];
    const float* Wq   = (const float*)d_in[3];
    const float* Wout = (const float*)d_in[4];
    const float* ckw  = (const float*)d_in[5];
    const float* ckb  = (const float*)d_in[6];
    const float* cvw  = (const float*)d_in[7];
    const float* cvb  = (const float*)d_in[8];
    const float* cqw  = (const float*)d_in[9];
    const float* cqb  = (const float*)d_in[10];
    const float* wdec = (const float*)d_in[11];
    const float* bdec = (const float*)d_in[12];
    const float* wlr  = (const float*)d_in[13];
    const float* blr  = (const float*)d_in[14];
    const float* weta = (const float*)d_in[15];
    const float* beta = (const float*)d_in[16];
    const float* W1   = (const float*)d_in[17];
    const float* W2   = (const float*)d_in[18];
    float* out = (float*)d_out;

    float *proj, *kc, *vc, *qc, *ych, *yfl, *h1, *a1, *sd, *d1, *tb, *d2, *g1, *g2;
    float *Wd1, *M1, *Wd2, *M2;
    cudaGetSymbolAddress((void**)&proj, g_proj);
    cudaGetSymbolAddress((void**)&kc,   g_kc);
    cudaGetSymbolAddress((void**)&vc,   g_vc);
    cudaGetSymbolAddress((void**)&qc,   g_qc);
    cudaGetSymbolAddress((void**)&ych,  g_ych);
    cudaGetSymbolAddress((void**)&yfl,  g_yfl);
    cudaGetSymbolAddress((void**)&h1,   g_h1);
    cudaGetSymbolAddress((void**)&a1,   g_a1);
    cudaGetSymbolAddress((void**)&sd,   g_sd);
    cudaGetSymbolAddress((void**)&d1,   g_d1);
    cudaGetSymbolAddress((void**)&tb,   g_tb);
    cudaGetSymbolAddress((void**)&d2,   g_d2);
    cudaGetSymbolAddress((void**)&g1,   g_g1);
    cudaGetSymbolAddress((void**)&g2,   g_g2);
    cudaGetSymbolAddress((void**)&Wd1,  g_Wd1);
    cudaGetSymbolAddress((void**)&M1,   g_M1);
    cudaGetSymbolAddress((void**)&Wd2,  g_Wd2);
    cudaGetSymbolAddress((void**)&M2,   g_M2);

    const int nRH = R_ * H_;      // 524288
    const int nRD = R_ * D_;      // 262144
    const int nHD = H_ * D_;      // 524288

    zero_state_kernel<<<(nHD + 255) / 256, 256>>>();
    gates_kernel<<<NC_, 512>>>(x, wdec, bdec, wlr, blr, weta, beta);

    // projections + causal depthwise conv -> chunk-major k,v,q
    const int nTOT = BS_ * D_;
    launch_gemm(0, false, x, Wk, nullptr, proj, BS_, D_, D_);
    conv_chunk_kernel<<<(nTOT + 255) / 256, 256>>>(proj, ckw, ckb, kc);
    launch_gemm(0, false, x, Wv, nullptr, proj, BS_, D_, D_);
    conv_chunk_kernel<<<(nTOT + 255) / 256, 256>>>(proj, cvw, cvb, vc);
    launch_gemm(0, false, x, Wq, nullptr, proj, BS_, D_, D_);
    conv_chunk_kernel<<<(nTOT + 255) / 256, 256>>>(proj, cqw, cqb, qc);

    // sequential chunk scan
    for (int c = 0; c < NC_; c++) {
        const float* kcc = kc + (size_t)c * nRD;
        const float* vcc = vc + (size_t)c * nRD;
        const float* qcc = qc + (size_t)c * nRD;

        // h1 = Kc @ (W1+Wd1)^T ; a1 = silu(h1), sd = silu'(h1)
        launch_gemm(0, true, kcc, W1, Wd1, h1, R_, H_, D_);
        silu_fwd_kernel<<<(nRH + 255) / 256, 256>>>(h1, a1, sd, nRH);
        // pred = a1 @ (W2+Wd2)^T ; d2 = scale*clip(pred - v)
        launch_gemm(0, true, a1, W2, Wd2, d2, R_, D_, H_);
        make_d2_kernel<<<(nRD + 255) / 256, 256>>>(d2, vcc, nRD);
        // d1 = (d2 @ E2) * sd   (uses OLD Wd2 -> must precede update)
        launch_gemm(1, true, d2, W2, Wd2, d1, R_, H_, D_);
        mul_inplace_kernel<<<(nRH + 255) / 256, 256>>>(d1, sd, nRH);
        // grads
        launch_gemm(2, false, d2, a1, nullptr, g2, D_, H_, R_);   // g2[d,h]
        launch_gemm(2, false, d1, kcc, nullptr, g1, H_, D_, R_);  // g1[h,d]
        // momentum + decay updates
        apply_update_kernel<<<(nHD + 255) / 256, 256>>>(g2, M2, Wd2, c, nHD);
        apply_update_kernel<<<(nHD + 255) / 256, 256>>>(g1, M1, Wd1, c, nHD);
        // retrieval with updated weights
        launch_gemm(0, true, qcc, W1, Wd1, tb, R_, H_, D_);
        silu_inplace_kernel<<<(nRH + 255) / 256, 256>>>(tb, nRH);
        launch_gemm(0, true, tb, W2, Wd2, ych + (size_t)c * nRD, R_, D_, H_);
    }

    permute_y_kernel<<<(nTOT + 255) / 256, 256>>>();
    launch_gemm(0, false, yfl, Wout, nullptr, out, BS_, D_, D_);
}

// round 2
// speedup vs baseline: 2.1984x; 2.1984x over previous
#include <cuda_runtime.h>
#include <math.h>
#include <stdint.h>

// ---------------- problem dims ----------------
#define B_   8
#define S_   4096
#define D_   512
#define H_   1024
#define Kc_  4
#define CS_  64
#define NC_  64
#define BS_  (B_ * S_)      // 32768 tokens
#define R_   (B_ * CS_)     // 512 rows per chunk
#define ERR_CLIP  1.0f
#define GRAD_CLIP 1.0f
#define SCALE_    (2.0f / (float)CS_)   // 0.03125
#define SPLITK 4

// ---------------- device scratch (static: no runtime alloc) ----------------
__device__ float g_proj [(size_t)BS_ * D_];   // pre-conv projection scratch
__device__ float g_kc   [(size_t)BS_ * D_];   // chunk-major [NC][B][CS][D]
__device__ float g_vc   [(size_t)BS_ * D_];
__device__ float g_qc   [(size_t)BS_ * D_];
__device__ float g_ych  [(size_t)BS_ * D_];   // retrieval output, chunk-major
__device__ float g_yfl  [(size_t)BS_ * D_];   // flat [B,S,D]
__device__ float g_a1   [(size_t)R_ * H_];
__device__ float g_sd   [(size_t)R_ * H_];
__device__ float g_d1   [(size_t)R_ * H_];
__device__ float g_tb   [(size_t)R_ * H_];
__device__ float g_d2   [(size_t)R_ * D_];
__device__ float g_Wd1  [(size_t)H_ * D_];
__device__ float g_M1   [(size_t)H_ * D_];
__device__ float g_Wd2  [(size_t)D_ * H_];
__device__ float g_M2   [(size_t)D_ * H_];
__device__ float g_part [(size_t)SPLITK * R_ * H_];   // split-K partials (8MB)
__device__ float g_alpha[NC_];
__device__ float g_lrg  [NC_];
__device__ float g_eta  [NC_];

// ---------------- generic tiled fp32 GEMM with optional split-K ----------------
// MODE 0 (NT): C[M,N] = A[M,K] * B[N,K]^T
// MODE 1 (NN): C[M,N] = A[M,K] * B[K,N]
// MODE 2 (TN): C[M,N] = A[K,M]^T * B[K,N]
// BSUM: effective B element = B0[i] + B1[i]
// SPLIT>1: blockIdx.z = z computes K-slice [z*K/SPLIT, (z+1)*K/SPLIT) into C + z*M*N
#define TILE 64
#define BK   16

template <int MODE, bool BSUM, int SPLIT>
__global__ void __launch_bounds__(256)
gemm_kernel(const float* __restrict__ A, const float* __restrict__ B0,
            const float* __restrict__ B1, float* __restrict__ C,
            int M, int N, int K)
{
    __shared__ float As[BK][TILE + 4];
    __shared__ float Bs[BK][TILE + 4];
    const int tid = threadIdx.x;
    const int tx = tid & 15;          // 0..15 -> n frag (x4)
    const int ty = tid >> 4;          // 0..15 -> m frag (x4)
    const int m0 = blockIdx.y * TILE;
    const int n0 = blockIdx.x * TILE;
    const int z  = (SPLIT > 1) ? blockIdx.z : 0;
    const int kslice = K / SPLIT;
    const int kbeg = z * kslice;
    const int kend = kbeg + kslice;
    float* Cw = (SPLIT > 1) ? (C + (size_t)z * M * N) : C;

    float acc[4][4] = {};

    for (int k0 = kbeg; k0 < kend; k0 += BK) {
        // --- load A tile into As[k][m] ---
        if (MODE == 2) {
            const int kk = tid >> 4;
            const int mv = (tid & 15) << 2;
            const float4 a = *(const float4*)(A + (size_t)(k0 + kk) * M + m0 + mv);
            As[kk][mv + 0] = a.x; As[kk][mv + 1] = a.y;
            As[kk][mv + 2] = a.z; As[kk][mv + 3] = a.w;
        } else {
            const int mm = tid >> 2;
            const int kv = (tid & 3) << 2;
            const float4 a = *(const float4*)(A + (size_t)(m0 + mm) * K + k0 + kv);
            As[kv + 0][mm] = a.x; As[kv + 1][mm] = a.y;
            As[kv + 2][mm] = a.z; As[kv + 3][mm] = a.w;
        }
        // --- load B tile into Bs[k][n] ---
        if (MODE == 0) {
            const int nn = tid >> 2;
            const int kv = (tid & 3) << 2;
            const size_t off = (size_t)(n0 + nn) * K + k0 + kv;
            float4 b = *(const float4*)(B0 + off);
            if (BSUM) {
                const float4 c4 = *(const float4*)(B1 + off);
                b.x += c4.x; b.y += c4.y; b.z += c4.z; b.w += c4.w;
            }
            Bs[kv + 0][nn] = b.x; Bs[kv + 1][nn] = b.y;
            Bs[kv + 2][nn] = b.z; Bs[kv + 3][nn] = b.w;
        } else {
            const int kk = tid >> 4;
            const int nv = (tid & 15) << 2;
            const size_t off = (size_t)(k0 + kk) * N + n0 + nv;
            float4 b = *(const float4*)(B0 + off);
            if (BSUM) {
                const float4 c4 = *(const float4*)(B1 + off);
                b.x += c4.x; b.y += c4.y; b.z += c4.z; b.w += c4.w;
            }
            Bs[kk][nv + 0] = b.x; Bs[kk][nv + 1] = b.y;
            Bs[kk][nv + 2] = b.z; Bs[kk][nv + 3] = b.w;
        }
        __syncthreads();

#pragma unroll
        for (int kk = 0; kk < BK; kk++) {
            const float4 av = *(const float4*)&As[kk][ty << 2];
            const float4 bv = *(const float4*)&Bs[kk][tx << 2];
            acc[0][0] = fmaf(av.x, bv.x, acc[0][0]);
            acc[0][1] = fmaf(av.x, bv.y, acc[0][1]);
            acc[0][2] = fmaf(av.x, bv.z, acc[0][2]);
            acc[0][3] = fmaf(av.x, bv.w, acc[0][3]);
            acc[1][0] = fmaf(av.y, bv.x, acc[1][0]);
            acc[1][1] = fmaf(av.y, bv.y, acc[1][1]);
            acc[1][2] = fmaf(av.y, bv.z, acc[1][2]);
            acc[1][3] = fmaf(av.y, bv.w, acc[1][3]);
            acc[2][0] = fmaf(av.z, bv.x, acc[2][0]);
            acc[2][1] = fmaf(av.z, bv.y, acc[2][1]);
            acc[2][2] = fmaf(av.z, bv.z, acc[2][2]);
            acc[2][3] = fmaf(av.z, bv.w, acc[2][3]);
            acc[3][0] = fmaf(av.w, bv.x, acc[3][0]);
            acc[3][1] = fmaf(av.w, bv.y, acc[3][1]);
            acc[3][2] = fmaf(av.w, bv.z, acc[3][2]);
            acc[3][3] = fmaf(av.w, bv.w, acc[3][3]);
        }
        __syncthreads();
    }

#pragma unroll
    for (int i = 0; i < 4; i++) {
        const size_t m = (size_t)m0 + (ty << 2) + i;
        float4 o;
        o.x = acc[i][0]; o.y = acc[i][1]; o.z = acc[i][2]; o.w = acc[i][3];
        *(float4*)(Cw + m * N + n0 + (tx << 2)) = o;
    }
}

static void launch_gemm1(int mode, const float* A, const float* B0,
                         float* C, int M, int N, int K)
{
    dim3 grid(N / TILE, M / TILE), block(256);
    if (mode == 0) gemm_kernel<0, false, 1><<<grid, block>>>(A, B0, nullptr, C, M, N, K);
    else if (mode == 1) gemm_kernel<1, false, 1><<<grid, block>>>(A, B0, nullptr, C, M, N, K);
    else gemm_kernel<2, false, 1><<<grid, block>>>(A, B0, nullptr, C, M, N, K);
}

static void launch_gemm4(int mode, bool bsum, const float* A, const float* B0,
                         const float* B1, float* C, int M, int N, int K)
{
    dim3 grid(N / TILE, M / TILE, SPLITK), block(256);
    if (mode == 0) {
        if (bsum) gemm_kernel<0, true , SPLITK><<<grid, block>>>(A, B0, B1, C, M, N, K);
        else      gemm_kernel<0, false, SPLITK><<<grid, block>>>(A, B0, B1, C, M, N, K);
    } else if (mode == 1) {
        if (bsum) gemm_kernel<1, true , SPLITK><<<grid, block>>>(A, B0, B1, C, M, N, K);
        else      gemm_kernel<1, false, SPLITK><<<grid, block>>>(A, B0, B1, C, M, N, K);
    } else {
        if (bsum) gemm_kernel<2, true , SPLITK><<<grid, block>>>(A, B0, B1, C, M, N, K);
        else      gemm_kernel<2, false, SPLITK><<<grid, block>>>(A, B0, B1, C, M, N, K);
    }
}

// ---------------- fused split-K reduction epilogues ----------------
__device__ __forceinline__ float sigm(float x) { return 1.0f / (1.0f + __expf(-x)); }

__device__ __forceinline__ float4 sum4(const float4* __restrict__ p, int i, int n4)
{
    float4 a = p[i], b = p[i + n4], c = p[i + 2 * n4], d = p[i + 3 * n4];
    a.x += b.x + c.x + d.x;
    a.y += b.y + c.y + d.y;
    a.z += b.z + c.z + d.z;
    a.w += b.w + c.w + d.w;
    return a;
}

// a = silu(sum), sd = silu'(sum)
__global__ void epi_silu_kernel(const float4* __restrict__ p, float4* __restrict__ a,
                                float4* __restrict__ sd, int n4)
{
    const int i = blockIdx.x * blockDim.x + threadIdx.x;
    if (i >= n4) return;
    const float4 v = sum4(p, i, n4);
    float4 av, dv;
    {
        const float s = sigm(v.x); av.x = v.x * s; dv.x = s * (1.f + v.x * (1.f - s));
    }{
        const float s = sigm(v.y); av.y = v.y * s; dv.y = s * (1.f + v.y * (1.f - s));
    }{
        const float s = sigm(v.z); av.z = v.z * s; dv.z = s * (1.f + v.z * (1.f - s));
    }{
        const float s = sigm(v.w); av.w = v.w * s; dv.w = s * (1.f + v.w * (1.f - s));
    }
    a[i] = av; sd[i] = dv;
}

// out = silu(sum)
__global__ void epi_silu1_kernel(const float4* __restrict__ p, float4* __restrict__ o, int n4)
{
    const int i = blockIdx.x * blockDim.x + threadIdx.x;
    if (i >= n4) return;
    const float4 v = sum4(p, i, n4);
    float4 ov;
    ov.x = v.x * sigm(v.x); ov.y = v.y * sigm(v.y);
    ov.z = v.z * sigm(v.z); ov.w = v.w * sigm(v.w);
    o[i] = ov;
}

// d2 = SCALE * clip(sum - v, +-ERR_CLIP)
__global__ void epi_d2_kernel(const float4* __restrict__ p, const float4* __restrict__ v,
                              float4* __restrict__ o, int n4)
{
    const int i = blockIdx.x * blockDim.x + threadIdx.x;
    if (i >= n4) return;
    const float4 s = sum4(p, i, n4);
    const float4 vv = v[i];
    float4 ov;
    ov.x = SCALE_ * fminf(fmaxf(s.x - vv.x, -ERR_CLIP), ERR_CLIP);
    ov.y = SCALE_ * fminf(fmaxf(s.y - vv.y, -ERR_CLIP), ERR_CLIP);
    ov.z = SCALE_ * fminf(fmaxf(s.z - vv.z, -ERR_CLIP), ERR_CLIP);
    ov.w = SCALE_ * fminf(fmaxf(s.w - vv.w, -ERR_CLIP), ERR_CLIP);
    o[i] = ov;
}

// o = sum * b (d1 = backprop * silu')
__global__ void epi_mul_kernel(const float4* __restrict__ p, const float4* __restrict__ b,
                               float4* __restrict__ o, int n4)
{
    const int i = blockIdx.x * blockDim.x + threadIdx.x;
    if (i >= n4) return;
    const float4 s = sum4(p, i, n4);
    const float4 bv = b[i];
    float4 ov;
    ov.x = s.x * bv.x; ov.y = s.y * bv.y; ov.z = s.z * bv.z; ov.w = s.w * bv.w;
    o[i] = ov;
}

// gc = clip(sum); M = eta*M - lr*gc; Wd = (1-a)*Wd + M
__global__ void epi_update_kernel(const float4* __restrict__ p, float4* __restrict__ Mo,
                                  float4* __restrict__ Wd, int c, int n4)
{
    const int i = blockIdx.x * blockDim.x + threadIdx.x;
    if (i >= n4) return;
    const float a = g_alpha[c], l = g_lrg[c], e = g_eta[c];
    const float4 g = sum4(p, i, n4);
    float4 m = Mo[i], w = Wd[i];
    m.x = e * m.x - l * fminf(fmaxf(g.x, -GRAD_CLIP), GRAD_CLIP);
    m.y = e * m.y - l * fminf(fmaxf(g.y, -GRAD_CLIP), GRAD_CLIP);
    m.z = e * m.z - l * fminf(fmaxf(g.z, -GRAD_CLIP), GRAD_CLIP);
    m.w = e * m.w - l * fminf(fmaxf(g.w, -GRAD_CLIP), GRAD_CLIP);
    w.x = (1.f - a) * w.x + m.x;
    w.y = (1.f - a) * w.y + m.y;
    w.z = (1.f - a) * w.z + m.z;
    w.w = (1.f - a) * w.w + m.w;
    Mo[i] = m; Wd[i] = w;
}

// o = sum (retrieval write)
__global__ void epi_copy_kernel(const float4* __restrict__ p, float4* __restrict__ o, int n4)
{
    const int i = blockIdx.x * blockDim.x + threadIdx.x;
    if (i >= n4) return;
    o[i] = sum4(p, i, n4);
}

// ---------------- misc kernels ----------------
__global__ void zero_state_kernel()
{
    const size_t i = (size_t)blockIdx.x * blockDim.x + threadIdx.x;
    if (i < (size_t)H_ * D_) {
        g_Wd1[i] = 0.f; g_M1[i] = 0.f; g_Wd2[i] = 0.f; g_M2[i] = 0.f;
    }
}

// causal depthwise conv (left pad K-1), writes chunk-major [NC][B][CS][D]
__global__ void conv_chunk_kernel(const float* __restrict__ in, const float* __restrict__ w,
                                  const float* __restrict__ bias, float* __restrict__ out)
{
    const size_t i = (size_t)blockIdx.x * blockDim.x + threadIdx.x;
    if (i >= (size_t)BS_ * D_) return;
    const int d = (int)(i & (D_ - 1));
    const size_t bs = i >> 9;            // b*S + s
    const int s = (int)(bs & (S_ - 1));
    const int b = (int)(bs >> 12);
    float acc = bias[d];
#pragma unroll
    for (int j = 0; j < Kc_; j++) {
        const int sp = s - (Kc_ - 1) + j;
        if (sp >= 0)
            acc = fmaf(w[d * Kc_ + j], in[((size_t)b * S_ + sp) * D_ + d], acc);
    }
    const int c  = s >> 6;
    const int cs = s & 63;
    out[((((size_t)c * B_ + b) * CS_ + cs) << 9) + d] = acc;
}

// per-chunk scalar gates: sigmoid(x.w + b) mean-pooled over (B, CS)
__global__ void gates_kernel(const float* __restrict__ x,
                             const float* __restrict__ wd, const float* __restrict__ bd,
                             const float* __restrict__ wl, const float* __restrict__ bl,
                             const float* __restrict__ we, const float* __restrict__ be)
{
    const int c = blockIdx.x;
    const int t = threadIdx.x;          // 0..511
    const int b  = t >> 6;
    const int cs = t & 63;
    const float4* xr = (const float4*)(x + (((size_t)b * S_ + (size_t)c * CS_ + cs) << 9));
    const float4* w0 = (const float4*)wd;
    const float4* w1 = (const float4*)wl;
    const float4* w2 = (const float4*)we;
    float s0 = 0.f, s1 = 0.f, s2 = 0.f;
#pragma unroll 4
    for (int d = 0; d < D_ / 4; d++) {
        const float4 xv = xr[d];
        const float4 a0 = w0[d], a1 = w1[d], a2 = w2[d];
        s0 += xv.x * a0.x + xv.y * a0.y + xv.z * a0.z + xv.w * a0.w;
        s1 += xv.x * a1.x + xv.y * a1.y + xv.z * a1.z + xv.w * a1.w;
        s2 += xv.x * a2.x + xv.y * a2.y + xv.z * a2.z + xv.w * a2.w;
    }
    s0 = sigm(s0 + bd[0]);
    s1 = sigm(s1 + bl[0]);
    s2 = sigm(s2 + be[0]);

    __shared__ float r0[512], r1[512], r2[512];
    r0[t] = s0; r1[t] = s1; r2[t] = s2;
    __syncthreads();
    for (int off = 256; off > 0; off >>= 1) {
        if (t < off) { r0[t] += r0[t + off]; r1[t] += r1[t + off]; r2[t] += r2[t + off]; }
        __syncthreads();
    }
    if (t == 0) {
        g_alpha[c] = r0[0] * (1.0f / 512.0f);
        g_lrg[c]   = r1[0] * (1.0f / 512.0f);
        g_eta[c]   = r2[0] * (1.0f / 512.0f);
    }
}

// chunk-major -> flat [B,S,D]
__global__ void permute_y_kernel()
{
    const size_t i = (size_t)blockIdx.x * blockDim.x + threadIdx.x;
    if (i >= (size_t)BS_ * D_) return;
    const int d = (int)(i & (D_ - 1));
    const size_t r = i >> 9;
    const int s = (int)(r & (S_ - 1));
    const int b = (int)(r >> 12);
    const int c  = s >> 6;
    const int cs = s & 63;
    g_yfl[i] = g_ych[((((size_t)c * B_ + b) * CS_ + cs) << 9) + d];
}

// ---------------- entry point ----------------
extern "C" void kernel_launch(void* const* d_in, const int* in_sizes, int n_in,
                              void* d_out, int out_size)
{
    (void)in_sizes; (void)n_in; (void)out_size;
    const float* x    = (const float*)d_in[0];
    const float* Wk   = (const float*)d_in[1];
    const float* Wv   = (const float*)d_in[2];
    const float* Wq   = (const float*)d_in[3];
    const float* Wout = (const float*)d_in[4];
    const float* ckw  = (const float*)d_in[5];
    const float* ckb  = (const float*)d_in[6];
    const float* cvw  = (const float*)d_in[7];
    const float* cvb  = (const float*)d_in[8];
    const float* cqw  = (const float*)d_in[9];
    const float* cqb  = (const float*)d_in[10];
    const float* wdec = (const float*)d_in[11];
    const float* bdec = (const float*)d_in[12];
    const float* wlr  = (const float*)d_in[13];
    const float* blr  = (const float*)d_in[14];
    const float* weta = (const float*)d_in[15];
    const float* beta = (const float*)d_in[16];
    const float* W1   = (const float*)d_in[17];
    const float* W2   = (const float*)d_in[18];
    float* out = (float*)d_out;

    float *proj, *kc, *vc, *qc, *ych, *yfl, *a1, *sd, *d1, *tb, *d2, *part;
    float *Wd1, *M1, *Wd2, *M2;
    cudaGetSymbolAddress((void**)&proj, g_proj);
    cudaGetSymbolAddress((void**)&kc,   g_kc);
    cudaGetSymbolAddress((void**)&vc,   g_vc);
    cudaGetSymbolAddress((void**)&qc,   g_qc);
    cudaGetSymbolAddress((void**)&ych,  g_ych);
    cudaGetSymbolAddress((void**)&yfl,  g_yfl);
    cudaGetSymbolAddress((void**)&a1,   g_a1);
    cudaGetSymbolAddress((void**)&sd,   g_sd);
    cudaGetSymbolAddress((void**)&d1,   g_d1);
    cudaGetSymbolAddress((void**)&tb,   g_tb);
    cudaGetSymbolAddress((void**)&d2,   g_d2);
    cudaGetSymbolAddress((void**)&part, g_part);
    cudaGetSymbolAddress((void**)&Wd1,  g_Wd1);
    cudaGetSymbolAddress((void**)&M1,   g_M1);
    cudaGetSymbolAddress((void**)&Wd2,  g_Wd2);
    cudaGetSymbolAddress((void**)&M2,   g_M2);

    const int nRH = R_ * H_;      // 524288
    const int nRD = R_ * D_;      // 262144
    const int nHD = H_ * D_;      // 524288
    const int nRH4 = nRH / 4, nRD4 = nRD / 4, nHD4 = nHD / 4;
    const int EB = 256;

    zero_state_kernel<<<(nHD + 255) / 256, 256>>>();
    gates_kernel<<<NC_, 512>>>(x, wdec, bdec, wlr, blr, weta, beta);

    // projections + causal depthwise conv -> chunk-major k,v,q
    const int nTOT = BS_ * D_;
    launch_gemm1(0, x, Wk, proj, BS_, D_, D_);
    conv_chunk_kernel<<<(nTOT + 255) / 256, 256>>>(proj, ckw, ckb, kc);
    launch_gemm1(0, x, Wv, proj, BS_, D_, D_);
    conv_chunk_kernel<<<(nTOT + 255) / 256, 256>>>(proj, cvw, cvb, vc);
    launch_gemm1(0, x, Wq, proj, BS_, D_, D_);
    conv_chunk_kernel<<<(nTOT + 255) / 256, 256>>>(proj, cqw, cqb, qc);

    const float4* part4 = (const float4*)part;

    // sequential chunk scan
    for (int c = 0; c < NC_; c++) {
        const float* kcc = kc + (size_t)c * nRD;
        const float* vcc = vc + (size_t)c * nRD;
        const float* qcc = qc + (size_t)c * nRD;

        // h1 = Kc @ (W1+Wd1)^T ; a1 = silu, sd = silu'
        launch_gemm4(0, true, kcc, W1, Wd1, part, R_, H_, D_);
        epi_silu_kernel<<<(nRH4 + EB - 1) / EB, EB>>>(part4, (float4*)a1, (float4*)sd, nRH4);
        // pred = a1 @ (W2+Wd2)^T ; d2 = scale*clip(pred - v)
        launch_gemm4(0, true, a1, W2, Wd2, part, R_, D_, H_);
        epi_d2_kernel<<<(nRD4 + EB - 1) / EB, EB>>>(part4, (const float4*)vcc, (float4*)d2, nRD4);
        // d1 = (d2 @ E2) * sd   (uses OLD Wd2 -> precedes updates)
        launch_gemm4(1, true, d2, W2, Wd2, part, R_, H_, D_);
        epi_mul_kernel<<<(nRH4 + EB - 1) / EB, EB>>>(part4, (const float4*)sd, (float4*)d1, nRH4);
        // g2 = clip(d2^T @ a1) -> momentum+decay update of (M2, Wd2)
        launch_gemm4(2, false, d2, a1, nullptr, part, D_, H_, R_);
        epi_update_kernel<<<(nHD4 + EB - 1) / EB, EB>>>(part4, (float4*)M2, (float4*)Wd2, c, nHD4);
        // g1 = clip(d1^T @ Kc) -> update (M1, Wd1)
        launch_gemm4(2, false, d1, kcc, nullptr, part, H_, D_, R_);
        epi_update_kernel<<<(nHD4 + EB - 1) / EB, EB>>>(part4, (float4*)M1, (float4*)Wd1, c, nHD4);
        // retrieval with updated weights
        launch_gemm4(0, true, qcc, W1, Wd1, part, R_, H_, D_);
        epi_silu1_kernel<<<(nRH4 + EB - 1) / EB, EB>>>(part4, (float4*)tb, nRH4);
        launch_gemm4(0, true, tb, W2, Wd2, part, R_, D_, H_);
        epi_copy_kernel<<<(nRD4 + EB - 1) / EB, EB>>>(part4, (float4*)(ych + (size_t)c * nRD), nRD4);
    }

    permute_y_kernel<<<(nTOT + 255) / 256, 256>>>();
    launch_gemm1(0, yfl, Wout, out, BS_, D_, D_);
}